// round 5
// baseline (speedup 1.0000x reference)
#include <cuda_runtime.h>
#include <cuda_fp16.h>
#include <cstdint>

// ============================================================================
// RBFEuclidean: out[b,u] = ||x_b||^2 - 2 x@w + ||w_u||^2
// x: [65536,256] f32, w: [256,1024] f32, out: [65536,1024] f32
//
// compute_103 (non-'a') virtual arch => NO tcgen05. Use classic mma.sync
// (HMMA m16n8k16 fp16->f32) + ldmatrix + cp.async.
//
// Main kernel: 256 CTAs (M-tile 256), full-K A tile (fp16, 128KB) persistent
// in SMEM (x read once, converted f32->fp16 in kernel; x_sq from f32).
// 16 N-subtiles of 64; B [256x64] fp16 double-buffered cp.async from a
// prepped fp16 copy of w (L2-resident). Epilogue re-stages through SMEM for
// coalesced STG.128.
// ============================================================================

#define THREADS 256
#define MTILE   256
#define NSUB    64
#define NT      16
#define KTOT    256

#define OFF_XSQ    0            // 256 f32  = 1024 B
#define OFF_WSQ    1024         // 1024 f32 = 4096 B
#define OFF_STAGE  5120         // 8 warps * 2048 B = 16384
#define OFF_A      21504        // 256 rows * 512 B = 131072
#define OFF_B      152576       // 2 * 32768
#define BBUF_BYTES 32768
#define SMEM_BYTES 218112

__device__ __half g_w16[256 * 1024];   // w in [k][n] layout, fp16
__device__ float  g_wsq[1024];

// ---------------------------------------------------------------------------
__device__ __forceinline__ void cp_async16(uint32_t smem_addr, const void* gptr) {
    asm volatile("cp.async.cg.shared.global [%0], [%1], 16;"
                 :: "r"(smem_addr), "l"(__cvta_generic_to_global(gptr)) : "memory");
}
__device__ __forceinline__ void cp_commit() {
    asm volatile("cp.async.commit_group;" ::: "memory");
}
template <int N>
__device__ __forceinline__ void cp_wait() {
    asm volatile("cp.async.wait_group %0;" :: "n"(N) : "memory");
}

__device__ __forceinline__ void ldsm_x4(uint32_t* r, uint32_t addr) {
    asm volatile("ldmatrix.sync.aligned.m8n8.x4.shared.b16 {%0,%1,%2,%3}, [%4];"
                 : "=r"(r[0]), "=r"(r[1]), "=r"(r[2]), "=r"(r[3]) : "r"(addr));
}
__device__ __forceinline__ void ldsm_x4_t(uint32_t* r, uint32_t addr) {
    asm volatile("ldmatrix.sync.aligned.m8n8.x4.trans.shared.b16 {%0,%1,%2,%3}, [%4];"
                 : "=r"(r[0]), "=r"(r[1]), "=r"(r[2]), "=r"(r[3]) : "r"(addr));
}
__device__ __forceinline__ void mma16816(float* d, const uint32_t* a, const uint32_t* b) {
    asm volatile(
        "mma.sync.aligned.m16n8k16.row.col.f32.f16.f16.f32 "
        "{%0,%1,%2,%3}, {%4,%5,%6,%7}, {%8,%9}, {%0,%1,%2,%3};"
        : "+f"(d[0]), "+f"(d[1]), "+f"(d[2]), "+f"(d[3])
        : "r"(a[0]), "r"(a[1]), "r"(a[2]), "r"(a[3]), "r"(b[0]), "r"(b[1]));
}

// ---------------------------------------------------------------------------
// Prep: w -> fp16 copy (same [k][n] layout) + w_sq (f32)
// ---------------------------------------------------------------------------
__global__ void prep_w_kernel(const float* __restrict__ w) {
    int gid = blockIdx.x * 256 + threadIdx.x;    // 0..1023
    float acc = 0.f;
#pragma unroll 8
    for (int f = 0; f < 256; f++) {
        float v = w[(size_t)f * 1024 + gid];
        acc += v * v;
    }
    g_wsq[gid] = acc;
#pragma unroll 8
    for (int j = 0; j < 256; j++) {
        int i = gid + j * 1024;
        g_w16[i] = __float2half(w[i]);
    }
}

// ---------------------------------------------------------------------------
// Main kernel
// ---------------------------------------------------------------------------
__global__ void __launch_bounds__(THREADS, 1)
rbf_main_kernel(const float* __restrict__ x, float* __restrict__ out) {
    extern __shared__ char smem[];
    const uint32_t sb = (uint32_t)__cvta_generic_to_shared(smem);
    const int tid = threadIdx.x;
    const int wid = tid >> 5;
    const int lid = tid & 31;
    const size_t m_base = (size_t)blockIdx.x * MTILE;

    // --- prefetch B(0) ---
    {
#pragma unroll
        for (int i = 0; i < 8; i++) {
            int idx = tid + i * 256;          // 0..2047 (16B chunks)
            int k = idx >> 3, c = idx & 7;
            const __half* src = g_w16 + (size_t)k * 1024 + c * 8;
            uint32_t dst = sb + OFF_B + k * 128 + ((c ^ (k & 7)) << 4);
            cp_async16(dst, src);
        }
        cp_commit();
    }

    // --- w_sq to smem ---
    {
        float* wsq_s = (float*)(smem + OFF_WSQ);
#pragma unroll
        for (int i = 0; i < 4; i++) wsq_s[tid + i * 256] = g_wsq[tid + i * 256];
    }

    // --- A load: f32 -> fp16 into swizzled smem, x_sq in f32 ---
    {
        const int lo = lid & 7;
        const int rq = tid >> 3;              // 0..31
        const float4* xv = (const float4*)(x + m_base * KTOT);
        float* xsq_s = (float*)(smem + OFF_XSQ);
#pragma unroll 1
        for (int pass = 0; pass < 8; pass++) {
            int r = pass * 32 + rq;
            int rx = r & 7;
            uint32_t rowbase = (uint32_t)(OFF_A + r * 512);
            float acc = 0.f;
#pragma unroll
            for (int j = 0; j < 8; j++) {
                int c4 = lo + j * 8;          // 0..63 (float4 index in row)
                float4 v = xv[(size_t)r * 64 + c4];
                acc += v.x * v.x + v.y * v.y + v.z * v.z + v.w * v.w;
                __half2 h0 = __floats2half2_rn(v.x, v.y);
                __half2 h1 = __floats2half2_rn(v.z, v.w);
                uint32_t byte = rowbase + ((uint32_t)((c4 >> 1) ^ rx) << 4) + ((c4 & 1) << 3);
                uint2 u;
                u.x = *(uint32_t*)&h0;
                u.y = *(uint32_t*)&h1;
                *(uint2*)(smem + byte) = u;
            }
            acc += __shfl_xor_sync(0xffffffffu, acc, 1);
            acc += __shfl_xor_sync(0xffffffffu, acc, 2);
            acc += __shfl_xor_sync(0xffffffffu, acc, 4);
            if (lo == 0) xsq_s[r] = acc;
        }
    }
    __syncthreads();

    const int m0w = wid * 32;
    const float* xsq_s = (const float*)(smem + OFF_XSQ);

    // per-warp invariant address pieces
    const int arow0 = m0w + (lid & 15);
    const uint32_t aaddr0 = sb + OFF_A + arow0 * 512;
    const uint32_t aaddr1 = aaddr0 + 16 * 512;
    const int ahi = lid >> 4;        // k-half select
    const int asw = lid & 7;         // == row & 7 for both m-tiles

    uint32_t bofs[4];
#pragma unroll
    for (int p = 0; p < 4; p++) {
        int sub = lid >> 3;
        int jl = 2 * p + (sub >> 1);     // local n8 tile
        int h = sub & 1;                 // k8 half
        bofs[p] = (uint32_t)(h * 1024 + (lid & 7) * 128 + ((jl ^ (lid & 7)) << 4));
    }

    for (int nt = 0; nt < NT; nt++) {
        // prefetch B(nt+1) (overlaps this subtile's compute)
        if (nt + 1 < NT) {
            int nb = (nt + 1) & 1;
#pragma unroll
            for (int i = 0; i < 8; i++) {
                int idx = tid + i * 256;
                int k = idx >> 3, c = idx & 7;
                const __half* src = g_w16 + (size_t)k * 1024 + (nt + 1) * NSUB + c * 8;
                uint32_t dst = sb + OFF_B + nb * BBUF_BYTES + k * 128 + ((c ^ (k & 7)) << 4);
                cp_async16(dst, src);
            }
            cp_commit();
            cp_wait<1>();   // B(nt) complete; B(nt+1) may stay in flight
        } else {
            cp_wait<0>();
        }
        __syncthreads();

        float d[2][8][4];
#pragma unroll
        for (int mt = 0; mt < 2; mt++)
#pragma unroll
            for (int j = 0; j < 8; j++)
#pragma unroll
                for (int e = 0; e < 4; e++) d[mt][j][e] = 0.f;

        const uint32_t bbase = sb + OFF_B + (nt & 1) * BBUF_BYTES;

#pragma unroll 4
        for (int ks = 0; ks < 16; ks++) {
            uint32_t a[2][4];
            uint32_t swz = (uint32_t)((2 * ks + ahi) ^ asw) << 4;
            ldsm_x4(a[0], aaddr0 + swz);
            ldsm_x4(a[1], aaddr1 + swz);
            uint32_t b[8][2];
#pragma unroll
            for (int p = 0; p < 4; p++) {
                uint32_t r4[4];
                ldsm_x4_t(r4, bbase + ks * 2048 + bofs[p]);
                b[2 * p][0] = r4[0];
                b[2 * p][1] = r4[1];
                b[2 * p + 1][0] = r4[2];
                b[2 * p + 1][1] = r4[3];
            }
#pragma unroll
            for (int mt = 0; mt < 2; mt++)
#pragma unroll
                for (int j = 0; j < 8; j++)
                    mma16816(d[mt][j], a[mt], b[j]);
        }
        __syncthreads();

        // --- epilogue: stage 32x16 per warp, coalesced STG.128 ---
        char* stage = smem + OFF_STAGE + wid * 2048;
#pragma unroll 1
        for (int q = 0; q < 4; q++) {
#pragma unroll
            for (int mt = 0; mt < 2; mt++)
#pragma unroll
                for (int jj = 0; jj < 2; jj++) {
                    int j = 2 * q + jj;
                    int r0l = mt * 16 + (lid >> 2);
                    int cl = jj * 8 + (lid & 3) * 2;
                    uint32_t o0 = (uint32_t)(r0l * 64 + (((cl >> 2) ^ (r0l & 3)) << 4) + ((cl & 3) << 2));
                    int r1l = r0l + 8;
                    uint32_t o1 = (uint32_t)(r1l * 64 + (((cl >> 2) ^ (r1l & 3)) << 4) + ((cl & 3) << 2));
                    *(float2*)(stage + o0) = make_float2(d[mt][j][0], d[mt][j][1]);
                    *(float2*)(stage + o1) = make_float2(d[mt][j][2], d[mt][j][3]);
                }
            __syncwarp();
            int colg = nt * 64 + q * 16 + (lid & 3) * 4;
            float4 wq = *(const float4*)(smem + OFF_WSQ + colg * 4);
#pragma unroll
            for (int i = 0; i < 4; i++) {
                int r = i * 8 + (lid >> 2);
                uint32_t off = (uint32_t)(r * 64 + (((lid & 3) ^ (r & 3)) << 4));
                float4 v = *(const float4*)(stage + off);
                float xs = xsq_s[m0w + r];
                float4 o;
                o.x = fmaf(-2.f, v.x, xs + wq.x);
                o.y = fmaf(-2.f, v.y, xs + wq.y);
                o.z = fmaf(-2.f, v.z, xs + wq.z);
                o.w = fmaf(-2.f, v.w, xs + wq.w);
                *(float4*)(out + (m_base + m0w + r) * 1024 + colg) = o;
            }
            __syncwarp();
        }
    }
}

// ---------------------------------------------------------------------------
extern "C" void kernel_launch(void* const* d_in, const int* in_sizes, int n_in,
                              void* d_out, int out_size) {
    (void)in_sizes; (void)n_in; (void)out_size;
    const float* x = (const float*)d_in[0];
    const float* w = (const float*)d_in[1];
    float* out = (float*)d_out;

    cudaFuncSetAttribute(rbf_main_kernel,
                         cudaFuncAttributeMaxDynamicSharedMemorySize, SMEM_BYTES);

    prep_w_kernel<<<4, 256>>>(w);
    rbf_main_kernel<<<256, THREADS, SMEM_BYTES>>>(x, out);
}

// round 6
// speedup vs baseline: 1.3595x; 1.3595x over previous
#include <cuda_runtime.h>
#include <cuda_fp16.h>
#include <cstdint>

// ============================================================================
// RBFEuclidean: out[b,u] = ||x_b||^2 - 2 x@w + ||w_u||^2
// x: [65536,256] f32, w: [256,1024] f32, out: [65536,1024] f32
//
// compute_103 virtual arch => classic mma.sync (HMMA m16n8k16 fp16->f32).
// R6: 512 threads / 16 warps (4 per SMSP) for latency hiding; warp tile
// m32n32 (8 m-warps x 2 n-warps over 256x64). Full-K A tile persistent in
// SMEM; B double-buffered cp.async; slab-staged coalesced epilogue.
// ============================================================================

#define THREADS 512
#define MTILE   256
#define NSUB    64
#define NT      16
#define KTOT    256

#define OFF_XSQ    0             // 256 f32
#define OFF_WSQ    1024          // 1024 f32 -> end 5120
#define OFF_STAGE  5120          // 16 warps * 1280B = 20480 -> end 25600
#define OFF_A      25600         // 256 rows * 512B = 131072 -> end 156672
#define OFF_B      156672        // 2 * 32768 -> end 222208
#define BBUF_BYTES 32768
#define SMEM_BYTES 222208

__device__ __half g_w16[256 * 1024];   // w as [k][n], fp16
__device__ float  g_wsq[1024];

// ---------------------------------------------------------------------------
__device__ __forceinline__ void cp_async16(uint32_t smem_addr, const void* gptr) {
    asm volatile("cp.async.cg.shared.global [%0], [%1], 16;"
                 :: "r"(smem_addr), "l"(__cvta_generic_to_global(gptr)) : "memory");
}
__device__ __forceinline__ void cp_commit() {
    asm volatile("cp.async.commit_group;" ::: "memory");
}
template <int N>
__device__ __forceinline__ void cp_wait() {
    asm volatile("cp.async.wait_group %0;" :: "n"(N) : "memory");
}

__device__ __forceinline__ void ldsm_x4(uint32_t* r, uint32_t addr) {
    asm volatile("ldmatrix.sync.aligned.m8n8.x4.shared.b16 {%0,%1,%2,%3}, [%4];"
                 : "=r"(r[0]), "=r"(r[1]), "=r"(r[2]), "=r"(r[3]) : "r"(addr));
}
__device__ __forceinline__ void ldsm_x4_t(uint32_t* r, uint32_t addr) {
    asm volatile("ldmatrix.sync.aligned.m8n8.x4.trans.shared.b16 {%0,%1,%2,%3}, [%4];"
                 : "=r"(r[0]), "=r"(r[1]), "=r"(r[2]), "=r"(r[3]) : "r"(addr));
}
__device__ __forceinline__ void mma16816(float* d, const uint32_t* a, const uint32_t* b) {
    asm volatile(
        "mma.sync.aligned.m16n8k16.row.col.f32.f16.f16.f32 "
        "{%0,%1,%2,%3}, {%4,%5,%6,%7}, {%8,%9}, {%0,%1,%2,%3};"
        : "+f"(d[0]), "+f"(d[1]), "+f"(d[2]), "+f"(d[3])
        : "r"(a[0]), "r"(a[1]), "r"(a[2]), "r"(a[3]), "r"(b[0]), "r"(b[1]));
}

// ---------------------------------------------------------------------------
// Prep: w -> fp16 copy + w_sq (f32). 64 blocks x 256 threads.
// ---------------------------------------------------------------------------
__global__ void prep_w_kernel(const float* __restrict__ w) {
    int t = blockIdx.x * 256 + threadIdx.x;      // 0..16383
    // fp16 conversion: 262144 elems, 16 per thread, coalesced
#pragma unroll
    for (int i = 0; i < 16; i++) {
        int idx = t + i * 16384;
        g_w16[idx] = __float2half(w[idx]);
    }
    // w_sq: first 1024 threads (blocks 0-3), coalesced column sums
    if (t < 1024) {
        float acc = 0.f;
#pragma unroll 8
        for (int f = 0; f < 256; f++) {
            float v = w[(size_t)f * 1024 + t];
            acc += v * v;
        }
        g_wsq[t] = acc;
    }
}

// ---------------------------------------------------------------------------
// Main kernel
// ---------------------------------------------------------------------------
__global__ void __launch_bounds__(THREADS, 1)
rbf_main_kernel(const float* __restrict__ x, float* __restrict__ out) {
    extern __shared__ char smem[];
    const uint32_t sb = (uint32_t)__cvta_generic_to_shared(smem);
    const int tid = threadIdx.x;
    const int wid = tid >> 5;
    const int lid = tid & 31;
    const int wm = wid >> 1;          // m-warp 0..7 (32 rows each)
    const int wn = wid & 1;           // n-warp 0..1 (32 cols each)
    const size_t m_base = (size_t)blockIdx.x * MTILE;

    // --- prefetch B(0): 2048 x 16B, 4 per thread ---
#pragma unroll
    for (int i = 0; i < 4; i++) {
        int idx = tid + i * 512;
        int k = idx >> 3, c = idx & 7;
        const __half* src = g_w16 + (size_t)k * 1024 + c * 8;
        uint32_t dst = sb + OFF_B + k * 128 + ((c ^ (k & 7)) << 4);
        cp_async16(dst, src);
    }
    cp_commit();

    // --- w_sq to smem ---
    {
        float* wsq_s = (float*)(smem + OFF_WSQ);
        wsq_s[tid] = g_wsq[tid];
        wsq_s[tid + 512] = g_wsq[tid + 512];
    }

    // --- A load: f32 -> fp16 swizzled smem, x_sq in f32 (8 threads/row) ---
    {
        const int lo = tid & 7;
        const int rq = tid >> 3;              // 0..63
        const float4* xv = (const float4*)(x + m_base * KTOT);
        float* xsq_s = (float*)(smem + OFF_XSQ);
#pragma unroll 1
        for (int pass = 0; pass < 4; pass++) {
            int r = pass * 64 + rq;
            int rx = r & 7;
            uint32_t rowbase = (uint32_t)(OFF_A + r * 512);
            float acc = 0.f;
#pragma unroll
            for (int j = 0; j < 8; j++) {
                int c4 = lo + j * 8;          // float4 index 0..63
                float4 v = xv[(size_t)r * 64 + c4];
                acc += v.x * v.x + v.y * v.y + v.z * v.z + v.w * v.w;
                __half2 h0 = __floats2half2_rn(v.x, v.y);
                __half2 h1 = __floats2half2_rn(v.z, v.w);
                uint32_t byte = rowbase + ((uint32_t)((c4 >> 1) ^ rx) << 4) + ((c4 & 1) << 3);
                uint2 u;
                u.x = *(uint32_t*)&h0;
                u.y = *(uint32_t*)&h1;
                *(uint2*)(smem + byte) = u;
            }
            acc += __shfl_xor_sync(0xffffffffu, acc, 1);
            acc += __shfl_xor_sync(0xffffffffu, acc, 2);
            acc += __shfl_xor_sync(0xffffffffu, acc, 4);
            if (lo == 0) xsq_s[r] = acc;
        }
    }
    __syncthreads();

    const float* xsq_s = (const float*)(smem + OFF_XSQ);
    const float* wsq_s = (const float*)(smem + OFF_WSQ);

    // A addressing (per warp): rows wm*32 + (lid&15), +16
    const uint32_t aaddr0 = sb + OFF_A + (uint32_t)(wm * 32 + (lid & 15)) * 512;
    const uint32_t aaddr1 = aaddr0 + 16 * 512;
    const int ahi = lid >> 4;
    const int asw = lid & 7;

    // B ldsm offsets: 2 x ldsm_x4_t cover n32 (tiles wn*4 .. wn*4+3)
    uint32_t bofs[2];
    {
        int sub = lid >> 3;
#pragma unroll
        for (int p = 0; p < 2; p++) {
            int jl = wn * 4 + 2 * p + (sub >> 1);
            bofs[p] = (uint32_t)((sub & 1) * 1024 + (lid & 7) * 128 + ((jl ^ (lid & 7)) << 4));
        }
    }

    float* stageF = (float*)(smem + OFF_STAGE + wid * 1280);   // 8 rows x 40 f32

    for (int nt = 0; nt < NT; nt++) {
        // prefetch B(nt+1) (buffer (nt+1)&1 free: last read in compute nt-1,
        // protected by the post-compute syncthreads)
        if (nt + 1 < NT) {
#pragma unroll
            for (int i = 0; i < 4; i++) {
                int idx = tid + i * 512;
                int k = idx >> 3, c = idx & 7;
                const __half* src = g_w16 + (size_t)k * 1024 + (nt + 1) * NSUB + c * 8;
                uint32_t dst = sb + OFF_B + ((nt + 1) & 1) * BBUF_BYTES
                             + k * 128 + ((c ^ (k & 7)) << 4);
                cp_async16(dst, src);
            }
            cp_commit();
            cp_wait<1>();
        } else {
            cp_wait<0>();
        }
        __syncthreads();

        float d[2][4][4];
#pragma unroll
        for (int mt = 0; mt < 2; mt++)
#pragma unroll
            for (int j = 0; j < 4; j++)
#pragma unroll
                for (int e = 0; e < 4; e++) d[mt][j][e] = 0.f;

        const uint32_t bbase = sb + OFF_B + (nt & 1) * BBUF_BYTES;

#pragma unroll 4
        for (int ks = 0; ks < 16; ks++) {
            uint32_t a[2][4];
            uint32_t swz = (uint32_t)((2 * ks + ahi) ^ asw) << 4;
            ldsm_x4(a[0], aaddr0 + swz);
            ldsm_x4(a[1], aaddr1 + swz);
            uint32_t b[4][2];
#pragma unroll
            for (int p = 0; p < 2; p++) {
                uint32_t r4[4];
                ldsm_x4_t(r4, bbase + ks * 2048 + bofs[p]);
                b[2 * p][0] = r4[0];
                b[2 * p][1] = r4[1];
                b[2 * p + 1][0] = r4[2];
                b[2 * p + 1][1] = r4[3];
            }
#pragma unroll
            for (int mt = 0; mt < 2; mt++)
#pragma unroll
                for (int j = 0; j < 4; j++)
                    mma16816(d[mt][j], a[mt], b[j]);
        }
        __syncthreads();   // all B(nt) reads done -> buffer reusable next iter

        // --- epilogue (per-warp): 4 slabs of 8 rows through stage ---
        const int col0 = nt * 64 + wn * 32;
        const int cql = (lid & 7) * 4;
        const float4 wq = *(const float4*)(wsq_s + col0 + cql);
#pragma unroll 1
        for (int s = 0; s < 4; s++) {
            const int mt = s >> 1, h = s & 1;
#pragma unroll
            for (int j = 0; j < 4; j++) {
                *(float2*)&stageF[(lid >> 2) * 40 + j * 8 + (lid & 3) * 2] =
                    make_float2(d[mt][j][2 * h], d[mt][j][2 * h + 1]);
            }
            __syncwarp();
#pragma unroll
            for (int p = 0; p < 2; p++) {
                int rl = p * 4 + (lid >> 3);
                float4 v = *(const float4*)&stageF[rl * 40 + cql];
                int grow = wm * 32 + s * 8 + rl;
                float xs = xsq_s[grow];
                float4 o;
                o.x = fmaf(-2.f, v.x, xs + wq.x);
                o.y = fmaf(-2.f, v.y, xs + wq.y);
                o.z = fmaf(-2.f, v.z, xs + wq.z);
                o.w = fmaf(-2.f, v.w, xs + wq.w);
                *(float4*)(out + (m_base + grow) * 1024 + col0 + cql) = o;
            }
            __syncwarp();
        }
    }
}

// ---------------------------------------------------------------------------
extern "C" void kernel_launch(void* const* d_in, const int* in_sizes, int n_in,
                              void* d_out, int out_size) {
    (void)in_sizes; (void)n_in; (void)out_size;
    const float* x = (const float*)d_in[0];
    const float* w = (const float*)d_in[1];
    float* out = (float*)d_out;

    cudaFuncSetAttribute(rbf_main_kernel,
                         cudaFuncAttributeMaxDynamicSharedMemorySize, SMEM_BYTES);

    prep_w_kernel<<<64, 256>>>(w);
    rbf_main_kernel<<<256, THREADS, SMEM_BYTES>>>(x, out);
}